// round 7
// baseline (speedup 1.0000x reference)
#include <cuda_runtime.h>

// Input:  image [256, 384, 384] float32   (i, j, c')
// Output: out   [1, 384, 320, 512] float32 (j, a, c)
//
// c: 384 -> 512 (x4/3): outputs 4K..4K+3 <- inputs 3K-1..3K+3,
//    fixed weights {0.875, 0.625, 0.375, 0.125}
// a: 256 -> 320 (x5/4): outputs 5m..5m+4 <- rows 4m-1..4m+4,
//    fixed weights {0.9, 0.7, 0.5, 0.3, 0.1}
// Boundary clamps degenerate (x[i]==x[i+1]) so fixed weights hold everywhere.
//
// R7: c-lerp during staging. Smem holds c-RESIZED rows (512 floats each).
//   Phase 1: 320 tasks (10 rows x 32 segments); each task = 3 LDG.128 +
//            2 boundary LDG.32 (L1 hits), 16-wide c-lerp, 4 STS.128.
//   Phase 2: thread (k,y): 6 aligned LDS.128 + a-lerp + 5 STG.128 (__stcs).

#define D0 256
#define D1 384
#define D2 384
#define S0 320
#define S1 384
#define S2 512

#define ROWS_SM 10
#define THREADS 256

__global__ __launch_bounds__(THREADS)
void resize3d_kernel(const float* __restrict__ in, float* __restrict__ out) {
    __shared__ float sm[ROWS_SM][S2];   // c-resized rows

    const int tid = threadIdx.x;
    const int m2 = blockIdx.x;      // 0..31: pair of a-groups
    const int j  = blockIdx.y;      // 0..383

    // ---- Phase 1: stage + c-lerp 10 rows (tasks: t=row, seg=16-col chunk) ----
    {
        const int base_row = 8 * m2 - 1;
        #pragma unroll
        for (int idx = tid; idx < ROWS_SM * 32; idx += THREADS) {
            int t   = idx >> 5;          // 0..9
            int seg = idx & 31;          // 0..31: output cols 16seg..16seg+15
            int g = min(max(base_row + t, 0), D0 - 1);
            const float* r = in + ((size_t)g * D1 + j) * D2 + 12 * seg;

            float4 A = __ldg((const float4*)r + 0);
            float4 B = __ldg((const float4*)r + 1);
            float4 C = __ldg((const float4*)r + 2);
            float xm1 = (seg == 0)  ? A.x : __ldg(r - 1);   // col clamp(12seg-1,0)
            float x12 = (seg == 31) ? C.w : __ldg(r + 12);  // col min(12seg+12,383)

            float x[14] = {xm1, A.x, A.y, A.z, A.w, B.x, B.y, B.z, B.w,
                           C.x, C.y, C.z, C.w, x12};
            float4* srow = (float4*)&sm[t][16 * seg];
            #pragma unroll
            for (int gg = 0; gg < 4; ++gg) {
                const float* tp = x + 3 * gg;     // taps tp[0..4]
                float4 o;
                o.x = tp[0] + 0.875f * (tp[1] - tp[0]);
                o.y = tp[1] + 0.625f * (tp[2] - tp[1]);
                o.z = tp[2] + 0.375f * (tp[3] - tp[2]);
                o.w = tp[3] + 0.125f * (tp[4] - tp[3]);
                srow[gg] = o;
            }
        }
    }
    __syncthreads();

    // ---- Phase 2: a-lerp + streaming stores ----
    const int k = tid & 127;        // c-group 0..127 -> output cols 4k..4k+3
    const int y = tid >> 7;         // 0..1: a-group within the pair
    const int m = 2 * m2 + y;
    const int t0 = 4 * y;           // smem slots t0..t0+5 = rows 4m-1..4m+4

    float4 L[6];
    #pragma unroll
    for (int t = 0; t < 6; ++t)
        L[t] = ((const float4*)sm[t0 + t])[k];

    float4* op = (float4*)(out + ((size_t)j * S0 + 5 * m) * S2 + 4 * k);
    const float wa[5] = {0.9f, 0.7f, 0.5f, 0.3f, 0.1f};

    #pragma unroll
    for (int s = 0; s < 5; ++s) {
        float w = wa[s];
        float4 o;
        o.x = L[s].x + w * (L[s + 1].x - L[s].x);
        o.y = L[s].y + w * (L[s + 1].y - L[s].y);
        o.z = L[s].z + w * (L[s + 1].z - L[s].z);
        o.w = L[s].w + w * (L[s + 1].w - L[s].w);
        __stcs(op, o);
        op += S2 / 4;
    }
}

extern "C" void kernel_launch(void* const* d_in, const int* in_sizes, int n_in,
                              void* d_out, int out_size) {
    (void)in_sizes; (void)n_in; (void)out_size;
    const float* in = (const float*)d_in[0];
    float* out = (float*)d_out;

    dim3 grid(S0 / 5 / 2, S1, 1);   // (a-group pairs fastest, j)
    dim3 block(THREADS, 1, 1);
    resize3d_kernel<<<grid, block>>>(in, out);
}

// round 8
// speedup vs baseline: 1.1661x; 1.1661x over previous
#include <cuda_runtime.h>
#include <cuda_pipeline.h>

// Input:  image [256, 384, 384] float32   (i, j, c')
// Output: out   [1, 384, 320, 512] float32 (j, a, c)
//
// c: 384 -> 512 (x4/3): outputs 4k..4k+3 <- inputs 3k-1..3k+3,
//    fixed weights {0.875, 0.625, 0.375, 0.125}
// a: 256 -> 320 (x5/4): outputs 5m..5m+4 <- rows 4m-1..4m+4,
//    fixed weights {0.9, 0.7, 0.5, 0.3, 0.1}
// Boundary clamps degenerate (x[i]==x[i+1]) so fixed weights hold everywhere.
//
// R8: R5 tiling, made persistent over 4 windows with a cp.async double-buffered
// pipeline. Window w = 2 a-groups (10 input rows, staged lane-contiguous).
// While computing window w, cp.async prefetches window w+1.

#define D0 256
#define D1 384
#define D2 384
#define S0 320
#define S1 384
#define S2 512

#define THREADS 256
#define WINDOWS 4           // a-groups per block = 2 * WINDOWS = 8
#define ROWS_SM 10          // rows per window

__global__ __launch_bounds__(THREADS, 7)
void resize3d_kernel(const float* __restrict__ in, float* __restrict__ out) {
    __shared__ float sm[2][ROWS_SM][D2];    // 30720 B

    const int tid = threadIdx.x;
    const int m8  = blockIdx.x;     // 0..7: octet of a-groups
    const int j   = blockIdx.y;     // 0..383

    // issue async staging of window w into buffer w&1
    auto issue = [&](int w) {
        const int base_row = 32 * m8 + 8 * w - 1;
        float* dst = &sm[w & 1][0][0];
        for (int idx = tid; idx < ROWS_SM * (D2 / 4); idx += THREADS) {
            int t = idx / (D2 / 4);
            int q = idx % (D2 / 4);
            int g = min(max(base_row + t, 0), D0 - 1);
            __pipeline_memcpy_async(
                dst + (t * D2 + 4 * q),
                in + ((size_t)g * D1 + j) * D2 + 4 * q,
                16);
        }
        __pipeline_commit();
    };

    issue(0);

    const int k = tid & 127;        // c-group 0..127 -> output cols 4k..4k+3
    const int y = tid >> 7;         // 0..1: a-group within window
    const int col0 = max(3 * k - 1, 0);
    const int col1 = 3 * k;
    const int col4 = min(3 * k + 3, D2 - 1);
    const int t0 = 4 * y;
    const float wa[5] = {0.9f, 0.7f, 0.5f, 0.3f, 0.1f};

    #pragma unroll
    for (int w = 0; w < WINDOWS; ++w) {
        if (w + 1 < WINDOWS) issue(w + 1);
        __pipeline_wait_prior((w + 1 < WINDOWS) ? 1 : 0);
        __syncthreads();

        const float (*buf)[D2] = sm[w & 1];
        const int m = 8 * m8 + 2 * w + y;

        float l[6][4];
        #pragma unroll
        for (int t = 0; t < 6; ++t) {
            const float* r = buf[t0 + t];
            float x0 = r[col0];
            float x1 = r[col1];
            float x2 = r[col1 + 1];
            float x3 = r[col1 + 2];
            float x4 = r[col4];
            l[t][0] = x0 + 0.875f * (x1 - x0);
            l[t][1] = x1 + 0.625f * (x2 - x1);
            l[t][2] = x2 + 0.375f * (x3 - x2);
            l[t][3] = x3 + 0.125f * (x4 - x3);
        }

        float4* op = (float4*)(out + ((size_t)j * S0 + 5 * m) * S2 + 4 * k);
        #pragma unroll
        for (int s = 0; s < 5; ++s) {
            float ww = wa[s];
            float4 o;
            o.x = l[s][0] + ww * (l[s + 1][0] - l[s][0]);
            o.y = l[s][1] + ww * (l[s + 1][1] - l[s][1]);
            o.z = l[s][2] + ww * (l[s + 1][2] - l[s][2]);
            o.w = l[s][3] + ww * (l[s + 1][3] - l[s][3]);
            __stcs(op, o);
            op += S2 / 4;
        }

        __syncthreads();   // everyone done reading buf[w&1] before it's refilled at w+2
    }
}

extern "C" void kernel_launch(void* const* d_in, const int* in_sizes, int n_in,
                              void* d_out, int out_size) {
    (void)in_sizes; (void)n_in; (void)out_size;
    const float* in = (const float*)d_in[0];
    float* out = (float*)d_out;

    dim3 grid(S0 / 5 / (2 * WINDOWS), S1, 1);   // (a-group octets fastest, j)
    dim3 block(THREADS, 1, 1);
    resize3d_kernel<<<grid, block>>>(in, out);
}

// round 9
// speedup vs baseline: 1.3540x; 1.1611x over previous
#include <cuda_runtime.h>

// Input:  image [256, 384, 384] float32   (i, j, c')
// Output: out   [1, 384, 320, 512] float32 (j, a, c)
//
// c: 384 -> 512 (x4/3): outputs 4k..4k+3 <- inputs 3k-1..3k+3,
//    fixed weights {0.875, 0.625, 0.375, 0.125}
// a: 256 -> 320 (x5/4): outputs 5m..5m+4 <- rows 4m-1..4m+4,
//    fixed weights {0.9, 0.7, 0.5, 0.3, 0.1}
// Boundary clamps degenerate (x[i]==x[i+1]) so fixed weights hold everywhere.
//
// R9 = R5 (best: 64.3us) + cache-policy split on staging loads:
//   rows shared with the neighboring block (g % 8 in {7, 0}) -> __ldg (cache)
//   single-use rows -> __ldcs (evict-first, don't pollute L2)

#define D0 256
#define D1 384
#define D2 384
#define S0 320
#define S1 384
#define S2 512

#define ROWS_SM 10          // input rows staged per block
#define THREADS 256

__global__ __launch_bounds__(THREADS)
void resize3d_kernel(const float* __restrict__ in, float* __restrict__ out) {
    __shared__ float sm[ROWS_SM][D2];

    const int tid = threadIdx.x;
    const int m2 = blockIdx.x;      // 0..31: pair of a-groups
    const int j  = blockIdx.y;      // 0..383

    // ---- Phase 1: coalesced float4 staging of 10 input rows ----
    // slot t <- input row clamp(8*m2 - 1 + t, 0, 255)
    {
        const int base_row = 8 * m2 - 1;
        #pragma unroll
        for (int idx = tid; idx < ROWS_SM * (D2 / 4); idx += THREADS) {
            int t = idx / (D2 / 4);
            int q = idx % (D2 / 4);
            int g = min(max(base_row + t, 0), D0 - 1);
            const float4* rp = (const float4*)(in + ((size_t)g * D1 + j) * D2);
            // slots 0,1 (rows 8m2-1, 8m2) and 8,9 (rows 8m2+7, 8m2+8) are
            // shared with the adjacent m2 block -> keep them cacheable;
            // interior rows are single-use -> streaming.
            float4 v = (t <= 1 || t >= 8) ? __ldg(rp + q) : __ldcs(rp + q);
            ((float4*)sm[t])[q] = v;
        }
    }
    __syncthreads();

    // ---- Phase 2: interpolate ----
    const int k = tid & 127;        // c-group 0..127 -> output cols 4k..4k+3
    const int y = tid >> 7;         // 0..1: a-group of the pair
    const int m = 2 * m2 + y;

    const int col0 = max(3 * k - 1, 0);
    const int col1 = 3 * k;
    const int col4 = min(3 * k + 3, D2 - 1);
    const int t0 = 4 * y;           // smem slots t0..t0+5 = rows 4m-1..4m+4

    float l[6][4];
    #pragma unroll
    for (int t = 0; t < 6; ++t) {
        const float* r = sm[t0 + t];
        float x0 = r[col0];
        float x1 = r[col1];
        float x2 = r[col1 + 1];
        float x3 = r[col1 + 2];
        float x4 = r[col4];
        l[t][0] = x0 + 0.875f * (x1 - x0);
        l[t][1] = x1 + 0.625f * (x2 - x1);
        l[t][2] = x2 + 0.375f * (x3 - x2);
        l[t][3] = x3 + 0.125f * (x4 - x3);
    }

    float4* op = (float4*)(out + ((size_t)j * S0 + 5 * m) * S2 + 4 * k);
    const float wa[5] = {0.9f, 0.7f, 0.5f, 0.3f, 0.1f};

    #pragma unroll
    for (int s = 0; s < 5; ++s) {
        float w = wa[s];
        float4 o;
        o.x = l[s][0] + w * (l[s + 1][0] - l[s][0]);
        o.y = l[s][1] + w * (l[s + 1][1] - l[s][1]);
        o.z = l[s][2] + w * (l[s + 1][2] - l[s][2]);
        o.w = l[s][3] + w * (l[s + 1][3] - l[s][3]);
        __stcs(op, o);
        op += S2 / 4;
    }
}

extern "C" void kernel_launch(void* const* d_in, const int* in_sizes, int n_in,
                              void* d_out, int out_size) {
    (void)in_sizes; (void)n_in; (void)out_size;
    const float* in = (const float*)d_in[0];
    float* out = (float*)d_out;

    dim3 grid(S0 / 5 / 2, S1, 1);   // (a-group pairs fastest, j)
    dim3 block(THREADS, 1, 1);
    resize3d_kernel<<<grid, block>>>(in, out);
}